// round 1
// baseline (speedup 1.0000x reference)
#include <cuda_runtime.h>

#define NN 50000
#define NE 1600000
#define HF 128     // H * F
#define NH 4
#define NF 32

// ---------------- device scratch (no runtime allocation allowed) ------------
__device__ float    g_feat[(size_t)NN * HF];   // projected features [N,128]
__device__ float    g_el[NN * NH];             // left attention halves [N,4]
__device__ float    g_er[NN * NH];             // right attention halves [N,4]
__device__ unsigned g_mkey[NN * NH];           // order-encoded segment max keys
__device__ float    g_denom[NN * NH];          // softmax denominators
__device__ float    g_e[(size_t)NE * NH];      // edge scores [E,4]
__device__ float    g_rst[(size_t)NN * HF];    // unnormalized aggregation [N,128]

// order-preserving float<->uint encoding so segment-max is a native REDG.MAX.U32
__device__ __forceinline__ unsigned fenc(float x) {
    unsigned b = __float_as_uint(x);
    return (b & 0x80000000u) ? ~b : (b | 0x80000000u);
}
__device__ __forceinline__ float fdec(unsigned k) {
    unsigned b = (k & 0x80000000u) ? (k ^ 0x80000000u) : ~k;
    return __uint_as_float(b);
}

__device__ __forceinline__ float lrelu(float x) {
    return x > 0.f ? x : 0.2f * x;
}

// ---------------- init: zero rst/denom, reset max keys ----------------------
__global__ void k_init() {
    int i = blockIdx.x * blockDim.x + threadIdx.x;
    if (i < NN * (HF / 4)) {
        ((float4*)g_rst)[i] = make_float4(0.f, 0.f, 0.f, 0.f);
    }
    if (i < NN) {
        ((float4*)g_denom)[i] = make_float4(0.f, 0.f, 0.f, 0.f);
        ((uint4*)g_mkey)[i]   = make_uint4(0u, 0u, 0u, 0u);  // decodes non-finite; any edge overwrites
    }
}

// ---------------- GEMM: feat = h @ W  (50000x128 @ 128x128) -----------------
// 64 rows x 128 cols per block, 256 threads, 8x4 register tile per thread.
__global__ void __launch_bounds__(256) k_gemm(const float* __restrict__ h,
                                              const float* __restrict__ W) {
    __shared__ float  As[16][68];      // [k][row], padded for banks + 16B align
    __shared__ float4 Ws[16 * 32];     // [k][col4]

    int tid = threadIdx.x;
    int tx = tid & 31;        // col group: cols tx*4 .. tx*4+3
    int ty = tid >> 5;        // row group: rows ty*8 .. ty*8+7
    int base = blockIdx.x * 64;

    int arow = tid >> 2;      // 0..63
    int aq   = tid & 3;       // k-quad

    float acc[8][4];
#pragma unroll
    for (int i = 0; i < 8; i++)
#pragma unroll
        for (int j = 0; j < 4; j++) acc[i][j] = 0.f;

    for (int k0 = 0; k0 < 128; k0 += 16) {
        // load A tile (transposed into smem)
        float4 av = make_float4(0.f, 0.f, 0.f, 0.f);
        int gr = base + arow;
        if (gr < NN) av = *(const float4*)&h[gr * 128 + k0 + aq * 4];
        As[aq * 4 + 0][arow] = av.x;
        As[aq * 4 + 1][arow] = av.y;
        As[aq * 4 + 2][arow] = av.z;
        As[aq * 4 + 3][arow] = av.w;
        // load W tile
        Ws[ty * 32 + tx]       = ((const float4*)W)[(k0 + ty) * 32 + tx];
        Ws[(ty + 8) * 32 + tx] = ((const float4*)W)[(k0 + ty + 8) * 32 + tx];
        __syncthreads();

#pragma unroll
        for (int kk = 0; kk < 16; kk++) {
            float4 a0 = *(const float4*)&As[kk][ty * 8];
            float4 a1 = *(const float4*)&As[kk][ty * 8 + 4];
            float4 b  = Ws[kk * 32 + tx];
            float av8[8] = {a0.x, a0.y, a0.z, a0.w, a1.x, a1.y, a1.z, a1.w};
#pragma unroll
            for (int i = 0; i < 8; i++) {
                acc[i][0] += av8[i] * b.x;
                acc[i][1] += av8[i] * b.y;
                acc[i][2] += av8[i] * b.z;
                acc[i][3] += av8[i] * b.w;
            }
        }
        __syncthreads();
    }

#pragma unroll
    for (int i = 0; i < 8; i++) {
        int gr = base + ty * 8 + i;
        if (gr < NN) {
            float4 v = make_float4(acc[i][0], acc[i][1], acc[i][2], acc[i][3]);
            ((float4*)g_feat)[gr * 32 + tx] = v;
        }
    }
}

// ---------------- per-node attention halves el/er ---------------------------
// one warp per node; lane l covers cols 4l..4l+3 (head = l/8)
__global__ void k_elr(const float* __restrict__ attn_l,
                      const float* __restrict__ attn_r) {
    int gw   = (blockIdx.x * blockDim.x + threadIdx.x) >> 5;
    int lane = threadIdx.x & 31;
    if (gw >= NN) return;
    float4 f  = ((const float4*)g_feat)[gw * 32 + lane];
    float4 al = ((const float4*)attn_l)[lane];
    float4 ar = ((const float4*)attn_r)[lane];
    float sl = f.x * al.x + f.y * al.y + f.z * al.z + f.w * al.w;
    float sr = f.x * ar.x + f.y * ar.y + f.z * ar.z + f.w * ar.w;
    // reduce within 8-lane head groups
#pragma unroll
    for (int d = 4; d >= 1; d >>= 1) {
        sl += __shfl_down_sync(0xffffffffu, sl, d, 8);
        sr += __shfl_down_sync(0xffffffffu, sr, d, 8);
    }
    if ((lane & 7) == 0) {
        g_el[gw * 4 + (lane >> 3)] = sl;
        g_er[gw * 4 + (lane >> 3)] = sr;
    }
}

// ---------------- edge pass 1: scores + segment max -------------------------
__global__ void k_edge1(const int* __restrict__ src, const int* __restrict__ dst) {
    int e = blockIdx.x * blockDim.x + threadIdx.x;
    if (e >= NE) return;
    int s = src[e], d = dst[e];
    float4 a = ((const float4*)g_el)[s];
    float4 b = ((const float4*)g_er)[d];
    float4 v;
    v.x = lrelu(a.x + b.x);
    v.y = lrelu(a.y + b.y);
    v.z = lrelu(a.z + b.z);
    v.w = lrelu(a.w + b.w);
    ((float4*)g_e)[e] = v;
    atomicMax(&g_mkey[d * 4 + 0], fenc(v.x));
    atomicMax(&g_mkey[d * 4 + 1], fenc(v.y));
    atomicMax(&g_mkey[d * 4 + 2], fenc(v.z));
    atomicMax(&g_mkey[d * 4 + 3], fenc(v.w));
}

// ---------------- edge pass 2: exp + unnormalized scatter -------------------
// one warp per edge; lane l handles feat cols 4l..4l+3 (head = l/8).
// rst accumulates ex * feat[src]; denom accumulates ex. Normalization deferred.
__global__ void __launch_bounds__(256) k_edge2(const int* __restrict__ src,
                                               const int* __restrict__ dst) {
    int gw   = (blockIdx.x * blockDim.x + threadIdx.x) >> 5;
    int lane = threadIdx.x & 31;
    if (gw >= NE) return;
    int s = src[gw], d = dst[gw];
    float4 ev = ((const float4*)g_e)[gw];
    uint4 mk  = ((const uint4*)g_mkey)[d];
    // any node reached here has >=1 incoming edge, so the max is finite
    float ex0 = __expf(ev.x - fdec(mk.x));
    float ex1 = __expf(ev.y - fdec(mk.y));
    float ex2 = __expf(ev.z - fdec(mk.z));
    float ex3 = __expf(ev.w - fdec(mk.w));
    if (lane < 4) {
        float exl = (lane == 0) ? ex0 : (lane == 1) ? ex1 : (lane == 2) ? ex2 : ex3;
        atomicAdd(&g_denom[d * 4 + lane], exl);
    }
    int hh = lane >> 3;
    float a = (hh == 0) ? ex0 : (hh == 1) ? ex1 : (hh == 2) ? ex2 : ex3;
    float4 f = ((const float4*)g_feat)[s * 32 + lane];
    float* p = (float*)&((float4*)g_rst)[d * 32 + lane];
    asm volatile("red.global.add.v4.f32 [%0], {%1, %2, %3, %4};"
                 :: "l"(p), "f"(f.x * a), "f"(f.y * a), "f"(f.z * a), "f"(f.w * a)
                 : "memory");
}

// ---------------- epilogue: normalize, +bias, relu, head mean ---------------
__global__ void k_out(const float* __restrict__ bias, float* __restrict__ out) {
    int i = blockIdx.x * blockDim.x + threadIdx.x;
    if (i >= NN * NF) return;
    int n = i >> 5;
    int f = i & 31;
    float4 dn = ((const float4*)g_denom)[n];
    float r0 = 1.f / fmaxf(dn.x, 1e-9f);
    float r1 = 1.f / fmaxf(dn.y, 1e-9f);
    float r2 = 1.f / fmaxf(dn.z, 1e-9f);
    float r3 = 1.f / fmaxf(dn.w, 1e-9f);
    const float* rp = &g_rst[n * 128];
    float acc = 0.f;
    acc += fmaxf(rp[f]       * r0 + bias[f],       0.f);
    acc += fmaxf(rp[32 + f]  * r1 + bias[32 + f],  0.f);
    acc += fmaxf(rp[64 + f]  * r2 + bias[64 + f],  0.f);
    acc += fmaxf(rp[96 + f]  * r3 + bias[96 + f],  0.f);
    out[i] = acc * 0.25f;
}

// ---------------- launch ----------------------------------------------------
extern "C" void kernel_launch(void* const* d_in, const int* in_sizes, int n_in,
                              void* d_out, int out_size) {
    const float* h    = (const float*)d_in[0];
    const float* W    = (const float*)d_in[1];
    const float* al   = (const float*)d_in[2];
    const float* ar   = (const float*)d_in[3];
    const float* bias = (const float*)d_in[4];
    const int*   src  = (const int*)d_in[5];
    const int*   dst  = (const int*)d_in[6];
    float*       out  = (float*)d_out;

    k_init<<<(NN * 32 + 255) / 256, 256>>>();
    k_gemm<<<(NN + 63) / 64, 256>>>(h, W);
    k_elr<<<(NN * 32 + 255) / 256, 256>>>(al, ar);
    k_edge1<<<(NE + 255) / 256, 256>>>(src, dst);
    k_edge2<<<NE / 8, 256>>>(src, dst);   // 1 warp per edge, 8 warps/block (NE % 8 == 0)
    k_out<<<(NN * NF + 255) / 256, 256>>>(bias, out);
}

// round 2
// speedup vs baseline: 1.5874x; 1.5874x over previous
#include <cuda_runtime.h>

#define NN 50000
#define NE 1600000
#define HF 128
#define NH 4
#define NF 32

// ---------------- device scratch ------------------------------------------
__device__ float g_feat[(size_t)NN * HF];   // projected features [N,128]
__device__ float g_el[NN * NH];             // left attention halves [N,4]
__device__ float g_er[NN * NH];             // right attention halves [N,4]
__device__ int   g_deg[NN];                 // in-degree histogram
__device__ int   g_off[NN + 1];             // CSR row offsets (by dst)
__device__ int   g_cursor[NN];              // scatter cursors (copy of offsets)
__device__ int   g_csr_src[NE];             // src ids grouped by dst

__device__ __forceinline__ float lrelu(float x) {
    return x > 0.f ? x : 0.2f * x;
}

// ---------------- init: zero degree histogram ------------------------------
__global__ void k_init() {
    int i = blockIdx.x * blockDim.x + threadIdx.x;
    if (i < NN) g_deg[i] = 0;
}

// ---------------- GEMM: feat = h @ W  (50000x128 @ 128x128) -----------------
__global__ void __launch_bounds__(256) k_gemm(const float* __restrict__ h,
                                              const float* __restrict__ W) {
    __shared__ float  As[16][68];
    __shared__ float4 Ws[16 * 32];

    int tid = threadIdx.x;
    int tx = tid & 31;
    int ty = tid >> 5;
    int base = blockIdx.x * 64;
    int arow = tid >> 2;
    int aq   = tid & 3;

    float acc[8][4];
#pragma unroll
    for (int i = 0; i < 8; i++)
#pragma unroll
        for (int j = 0; j < 4; j++) acc[i][j] = 0.f;

    for (int k0 = 0; k0 < 128; k0 += 16) {
        float4 av = make_float4(0.f, 0.f, 0.f, 0.f);
        int gr = base + arow;
        if (gr < NN) av = *(const float4*)&h[gr * 128 + k0 + aq * 4];
        As[aq * 4 + 0][arow] = av.x;
        As[aq * 4 + 1][arow] = av.y;
        As[aq * 4 + 2][arow] = av.z;
        As[aq * 4 + 3][arow] = av.w;
        Ws[ty * 32 + tx]       = ((const float4*)W)[(k0 + ty) * 32 + tx];
        Ws[(ty + 8) * 32 + tx] = ((const float4*)W)[(k0 + ty + 8) * 32 + tx];
        __syncthreads();

#pragma unroll
        for (int kk = 0; kk < 16; kk++) {
            float4 a0 = *(const float4*)&As[kk][ty * 8];
            float4 a1 = *(const float4*)&As[kk][ty * 8 + 4];
            float4 b  = Ws[kk * 32 + tx];
            float av8[8] = {a0.x, a0.y, a0.z, a0.w, a1.x, a1.y, a1.z, a1.w};
#pragma unroll
            for (int i = 0; i < 8; i++) {
                acc[i][0] += av8[i] * b.x;
                acc[i][1] += av8[i] * b.y;
                acc[i][2] += av8[i] * b.z;
                acc[i][3] += av8[i] * b.w;
            }
        }
        __syncthreads();
    }

#pragma unroll
    for (int i = 0; i < 8; i++) {
        int gr = base + ty * 8 + i;
        if (gr < NN)
            ((float4*)g_feat)[gr * 32 + tx] =
                make_float4(acc[i][0], acc[i][1], acc[i][2], acc[i][3]);
    }
}

// ---------------- per-node attention halves el/er ---------------------------
__global__ void k_elr(const float* __restrict__ attn_l,
                      const float* __restrict__ attn_r) {
    int gw   = (blockIdx.x * blockDim.x + threadIdx.x) >> 5;
    int lane = threadIdx.x & 31;
    if (gw >= NN) return;
    float4 f  = ((const float4*)g_feat)[gw * 32 + lane];
    float4 al = ((const float4*)attn_l)[lane];
    float4 ar = ((const float4*)attn_r)[lane];
    float sl = f.x * al.x + f.y * al.y + f.z * al.z + f.w * al.w;
    float sr = f.x * ar.x + f.y * ar.y + f.z * ar.z + f.w * ar.w;
#pragma unroll
    for (int d = 4; d >= 1; d >>= 1) {
        sl += __shfl_down_sync(0xffffffffu, sl, d, 8);
        sr += __shfl_down_sync(0xffffffffu, sr, d, 8);
    }
    if ((lane & 7) == 0) {
        g_el[gw * 4 + (lane >> 3)] = sl;
        g_er[gw * 4 + (lane >> 3)] = sr;
    }
}

// ---------------- CSR build: histogram ------------------------------------
__global__ void k_hist(const int* __restrict__ dst) {
    int e = blockIdx.x * blockDim.x + threadIdx.x;
    if (e < NE) atomicAdd(&g_deg[dst[e]], 1);
}

// ---------------- CSR build: single-block exclusive scan --------------------
__global__ void __launch_bounds__(1024) k_scan() {
    __shared__ int ssum[1024];
    const int C = (NN + 1023) / 1024;   // 49
    int t = threadIdx.x;
    int b0 = t * C;
    int local = 0;
    for (int i = 0; i < C; i++) {
        int idx = b0 + i;
        if (idx < NN) local += g_deg[idx];
    }
    ssum[t] = local;
    __syncthreads();
    for (int off = 1; off < 1024; off <<= 1) {
        int v = (t >= off) ? ssum[t - off] : 0;
        __syncthreads();
        ssum[t] += v;
        __syncthreads();
    }
    int run = (t > 0) ? ssum[t - 1] : 0;   // exclusive prefix
    for (int i = 0; i < C; i++) {
        int idx = b0 + i;
        if (idx < NN) {
            g_off[idx]    = run;
            g_cursor[idx] = run;
            run += g_deg[idx];
        }
    }
    if (t == 1023) g_off[NN] = ssum[1023];
}

// ---------------- CSR build: scatter src ids grouped by dst -----------------
__global__ void k_scatter(const int* __restrict__ src, const int* __restrict__ dst) {
    int e = blockIdx.x * blockDim.x + threadIdx.x;
    if (e >= NE) return;
    int d = dst[e];
    int pos = atomicAdd(&g_cursor[d], 1);
    g_csr_src[pos] = src[e];
}

// ---------------- fused aggregate: softmax + gather + epilogue --------------
// one warp per dst node. lane l covers cols 4l..4l+3 (head = l>>3).
__global__ void __launch_bounds__(256) k_agg(const float* __restrict__ bias,
                                             float* __restrict__ out) {
    __shared__ int   s_s[8][32];
    __shared__ float s_ex[8][4][32];

    int w    = (blockIdx.x * blockDim.x + threadIdx.x) >> 5;
    int lane = threadIdx.x & 31;
    int wl   = threadIdx.x >> 5;
    if (w >= NN) return;

    int start = g_off[w];
    int end   = g_off[w + 1];
    float4 erd = ((const float4*)g_er)[w];
    int hh = lane >> 3;

    float4 acc  = make_float4(0.f, 0.f, 0.f, 0.f);
    float4 dsum = make_float4(0.f, 0.f, 0.f, 0.f);

    for (int base = start; base < end; base += 32) {
        int e = base + lane;
        int s = 0;
        float4 ex4 = make_float4(0.f, 0.f, 0.f, 0.f);
        if (e < end) {
            s = __ldg(&g_csr_src[e]);
            float4 a = ((const float4*)g_el)[s];
            ex4.x = __expf(lrelu(a.x + erd.x));
            ex4.y = __expf(lrelu(a.y + erd.y));
            ex4.z = __expf(lrelu(a.z + erd.z));
            ex4.w = __expf(lrelu(a.w + erd.w));
            dsum.x += ex4.x; dsum.y += ex4.y; dsum.z += ex4.z; dsum.w += ex4.w;
        }
        s_s[wl][lane]     = s;
        s_ex[wl][0][lane] = ex4.x;
        s_ex[wl][1][lane] = ex4.y;
        s_ex[wl][2][lane] = ex4.z;
        s_ex[wl][3][lane] = ex4.w;
        __syncwarp();

        int cnt = end - base;
        if (cnt > 32) cnt = 32;
#pragma unroll 4
        for (int j = 0; j < cnt; j++) {
            int   sj = s_s[wl][j];
            float aj = s_ex[wl][hh][j];
            float4 f = ((const float4*)g_feat)[sj * 32 + lane];
            acc.x += f.x * aj;
            acc.y += f.y * aj;
            acc.z += f.z * aj;
            acc.w += f.w * aj;
        }
        __syncwarp();
    }

    // warp-allreduce denom (4 heads)
#pragma unroll
    for (int d = 16; d >= 1; d >>= 1) {
        dsum.x += __shfl_xor_sync(0xffffffffu, dsum.x, d);
        dsum.y += __shfl_xor_sync(0xffffffffu, dsum.y, d);
        dsum.z += __shfl_xor_sync(0xffffffffu, dsum.z, d);
        dsum.w += __shfl_xor_sync(0xffffffffu, dsum.w, d);
    }
    float dh = (hh == 0) ? dsum.x : (hh == 1) ? dsum.y : (hh == 2) ? dsum.z : dsum.w;
    float r  = 1.f / fmaxf(dh, 1e-9f);

    // per-head: normalize, +bias, relu
    float4 b4 = ((const float4*)bias)[lane];
    float4 v;
    v.x = fmaxf(acc.x * r + b4.x, 0.f);
    v.y = fmaxf(acc.y * r + b4.y, 0.f);
    v.z = fmaxf(acc.z * r + b4.z, 0.f);
    v.w = fmaxf(acc.w * r + b4.w, 0.f);

    // mean over heads: sum lanes l, l^8, l^16, l^24
#pragma unroll
    for (int d = 8; d <= 16; d <<= 1) {
        v.x += __shfl_xor_sync(0xffffffffu, v.x, d);
        v.y += __shfl_xor_sync(0xffffffffu, v.y, d);
        v.z += __shfl_xor_sync(0xffffffffu, v.z, d);
        v.w += __shfl_xor_sync(0xffffffffu, v.w, d);
    }
    if (lane < 8) {
        v.x *= 0.25f; v.y *= 0.25f; v.z *= 0.25f; v.w *= 0.25f;
        ((float4*)out)[w * 8 + lane] = v;
    }
}

// ---------------- launch ----------------------------------------------------
extern "C" void kernel_launch(void* const* d_in, const int* in_sizes, int n_in,
                              void* d_out, int out_size) {
    const float* h    = (const float*)d_in[0];
    const float* W    = (const float*)d_in[1];
    const float* al   = (const float*)d_in[2];
    const float* ar   = (const float*)d_in[3];
    const float* bias = (const float*)d_in[4];
    const int*   src  = (const int*)d_in[5];
    const int*   dst  = (const int*)d_in[6];
    float*       out  = (float*)d_out;

    k_init<<<(NN + 255) / 256, 256>>>();
    k_gemm<<<(NN + 63) / 64, 256>>>(h, W);
    k_elr<<<(NN * 32 + 255) / 256, 256>>>(al, ar);
    k_hist<<<(NE + 255) / 256, 256>>>(dst);
    k_scan<<<1, 1024>>>();
    k_scatter<<<(NE + 255) / 256, 256>>>(src, dst);
    k_agg<<<(NN * 32 + 255) / 256, 256>>>(bias, out);
}

// round 3
// speedup vs baseline: 1.7458x; 1.0998x over previous
#include <cuda_runtime.h>
#include <cuda_fp16.h>

#define NN 50000
#define NE 1600000
#define HF 128
#define NH 4
#define NF 32

// ---------------- device scratch ------------------------------------------
__device__ __half2 g_feath[(size_t)NN * 64];  // projected features fp16 [N,128]
__device__ float   g_el[NN * NH];             // left attention halves [N,4]
__device__ float   g_er[NN * NH];             // right attention halves [N,4]
__device__ int     g_deg[NN];                 // in-degree histogram
__device__ int     g_off[NN + 1];             // CSR row offsets (by dst)
__device__ int     g_cursor[NN];              // scatter cursors
__device__ int     g_csr_src[NE];             // src ids grouped by dst

__device__ __forceinline__ float lrelu(float x) {
    return x > 0.f ? x : 0.2f * x;
}

// ---------------- init: zero degree histogram ------------------------------
__global__ void k_init() {
    int i = blockIdx.x * blockDim.x + threadIdx.x;
    if (i < NN) g_deg[i] = 0;
}

// ---------------- GEMM: feat = h @ W, fused el/er epilogue ------------------
// 64 rows x 128 cols per block, 256 threads, 8x4 register tile per thread.
// Warp ty holds rows ty*8..ty*8+7, its 32 lanes cover all 128 cols.
__global__ void __launch_bounds__(256) k_gemm(const float* __restrict__ h,
                                              const float* __restrict__ W,
                                              const float* __restrict__ attn_l,
                                              const float* __restrict__ attn_r) {
    __shared__ float  As[16][68];
    __shared__ float4 Ws[16 * 32];

    int tid = threadIdx.x;
    int tx = tid & 31;        // lane: cols tx*4..tx*4+3, head hh = tx>>3
    int ty = tid >> 5;        // warp: rows ty*8..ty*8+7
    int base = blockIdx.x * 64;
    int arow = tid >> 2;
    int aq   = tid & 3;

    float acc[8][4];
#pragma unroll
    for (int i = 0; i < 8; i++)
#pragma unroll
        for (int j = 0; j < 4; j++) acc[i][j] = 0.f;

    for (int k0 = 0; k0 < 128; k0 += 16) {
        float4 av = make_float4(0.f, 0.f, 0.f, 0.f);
        int gr = base + arow;
        if (gr < NN) av = *(const float4*)&h[gr * 128 + k0 + aq * 4];
        As[aq * 4 + 0][arow] = av.x;
        As[aq * 4 + 1][arow] = av.y;
        As[aq * 4 + 2][arow] = av.z;
        As[aq * 4 + 3][arow] = av.w;
        Ws[ty * 32 + tx]       = ((const float4*)W)[(k0 + ty) * 32 + tx];
        Ws[(ty + 8) * 32 + tx] = ((const float4*)W)[(k0 + ty + 8) * 32 + tx];
        __syncthreads();

#pragma unroll
        for (int kk = 0; kk < 16; kk++) {
            float4 a0 = *(const float4*)&As[kk][ty * 8];
            float4 a1 = *(const float4*)&As[kk][ty * 8 + 4];
            float4 b  = Ws[kk * 32 + tx];
            float av8[8] = {a0.x, a0.y, a0.z, a0.w, a1.x, a1.y, a1.z, a1.w};
#pragma unroll
            for (int i = 0; i < 8; i++) {
                acc[i][0] += av8[i] * b.x;
                acc[i][1] += av8[i] * b.y;
                acc[i][2] += av8[i] * b.z;
                acc[i][3] += av8[i] * b.w;
            }
        }
        __syncthreads();
    }

    // epilogue: fp16 feat store + fused el/er
    float4 al = ((const float4*)attn_l)[tx];
    float4 ar = ((const float4*)attn_r)[tx];
    int hh = tx >> 3;

#pragma unroll
    for (int i = 0; i < 8; i++) {
        int gr = base + ty * 8 + i;
        bool valid = (gr < NN);

        __half2 h0 = __floats2half2_rn(acc[i][0], acc[i][1]);
        __half2 h1 = __floats2half2_rn(acc[i][2], acc[i][3]);
        if (valid) {
            uint2 u;
            u.x = *(unsigned*)&h0;
            u.y = *(unsigned*)&h1;
            ((uint2*)g_feath)[gr * 32 + tx] = u;
        }

        float pl = acc[i][0] * al.x + acc[i][1] * al.y + acc[i][2] * al.z + acc[i][3] * al.w;
        float pr = acc[i][0] * ar.x + acc[i][1] * ar.y + acc[i][2] * ar.z + acc[i][3] * ar.w;
#pragma unroll
        for (int d = 4; d >= 1; d >>= 1) {
            pl += __shfl_down_sync(0xffffffffu, pl, d, 8);
            pr += __shfl_down_sync(0xffffffffu, pr, d, 8);
        }
        if (valid && (tx & 7) == 0) {
            g_el[gr * 4 + hh] = pl;
            g_er[gr * 4 + hh] = pr;
        }
    }
}

// ---------------- CSR build: histogram ------------------------------------
__global__ void k_hist(const int* __restrict__ dst) {
    int e = blockIdx.x * blockDim.x + threadIdx.x;
    if (e < NE) atomicAdd(&g_deg[dst[e]], 1);
}

// ---------------- CSR build: single-block exclusive scan --------------------
__global__ void __launch_bounds__(1024) k_scan() {
    __shared__ int ssum[1024];
    const int C = (NN + 1023) / 1024;   // 49
    int t = threadIdx.x;
    int b0 = t * C;
    int local = 0;
    for (int i = 0; i < C; i++) {
        int idx = b0 + i;
        if (idx < NN) local += g_deg[idx];
    }
    ssum[t] = local;
    __syncthreads();
    for (int off = 1; off < 1024; off <<= 1) {
        int v = (t >= off) ? ssum[t - off] : 0;
        __syncthreads();
        ssum[t] += v;
        __syncthreads();
    }
    int run = (t > 0) ? ssum[t - 1] : 0;
    for (int i = 0; i < C; i++) {
        int idx = b0 + i;
        if (idx < NN) {
            g_off[idx]    = run;
            g_cursor[idx] = run;
            run += g_deg[idx];
        }
    }
    if (t == 1023) g_off[NN] = ssum[1023];
}

// ---------------- CSR build: scatter src ids grouped by dst -----------------
__global__ void k_scatter(const int* __restrict__ src, const int* __restrict__ dst) {
    int e = blockIdx.x * blockDim.x + threadIdx.x;
    if (e >= NE) return;
    int d = dst[e];
    int pos = atomicAdd(&g_cursor[d], 1);
    g_csr_src[pos] = src[e];
}

// ---------------- fused aggregate: softmax + fp16 gather + epilogue ---------
// one warp per dst node. lane l covers cols 4l..4l+3 (head = l>>3).
__global__ void __launch_bounds__(256) k_agg(const float* __restrict__ bias,
                                             float* __restrict__ out) {
    __shared__ int   s_s[8][32];
    __shared__ float s_ex[8][4][32];

    int w    = (blockIdx.x * blockDim.x + threadIdx.x) >> 5;
    int lane = threadIdx.x & 31;
    int wl   = threadIdx.x >> 5;
    if (w >= NN) return;

    int start = g_off[w];
    int end   = g_off[w + 1];
    float4 erd = ((const float4*)g_er)[w];
    int hh = lane >> 3;

    float4 acc  = make_float4(0.f, 0.f, 0.f, 0.f);
    float4 dsum = make_float4(0.f, 0.f, 0.f, 0.f);

    for (int base = start; base < end; base += 32) {
        int e = base + lane;
        int s = 0;
        float4 ex4 = make_float4(0.f, 0.f, 0.f, 0.f);
        if (e < end) {
            s = __ldg(&g_csr_src[e]);
            float4 a = ((const float4*)g_el)[s];
            ex4.x = __expf(lrelu(a.x + erd.x));
            ex4.y = __expf(lrelu(a.y + erd.y));
            ex4.z = __expf(lrelu(a.z + erd.z));
            ex4.w = __expf(lrelu(a.w + erd.w));
            dsum.x += ex4.x; dsum.y += ex4.y; dsum.z += ex4.z; dsum.w += ex4.w;
        }
        s_s[wl][lane]     = s;
        s_ex[wl][0][lane] = ex4.x;
        s_ex[wl][1][lane] = ex4.y;
        s_ex[wl][2][lane] = ex4.z;
        s_ex[wl][3][lane] = ex4.w;
        __syncwarp();

        int cnt = end - base;
        if (cnt > 32) cnt = 32;
#pragma unroll 4
        for (int j = 0; j < cnt; j++) {
            int   sj = s_s[wl][j];
            float aj = s_ex[wl][hh][j];
            uint2 u  = __ldg(&((const uint2*)g_feath)[sj * 32 + lane]);
            float2 f0 = __half22float2(*(__half2*)&u.x);
            float2 f1 = __half22float2(*(__half2*)&u.y);
            acc.x += f0.x * aj;
            acc.y += f0.y * aj;
            acc.z += f1.x * aj;
            acc.w += f1.y * aj;
        }
        __syncwarp();
    }

    // warp-allreduce denom (4 heads)
#pragma unroll
    for (int d = 16; d >= 1; d >>= 1) {
        dsum.x += __shfl_xor_sync(0xffffffffu, dsum.x, d);
        dsum.y += __shfl_xor_sync(0xffffffffu, dsum.y, d);
        dsum.z += __shfl_xor_sync(0xffffffffu, dsum.z, d);
        dsum.w += __shfl_xor_sync(0xffffffffu, dsum.w, d);
    }
    float dh = (hh == 0) ? dsum.x : (hh == 1) ? dsum.y : (hh == 2) ? dsum.z : dsum.w;
    float r  = 1.f / fmaxf(dh, 1e-9f);

    float4 b4 = ((const float4*)bias)[lane];
    float4 v;
    v.x = fmaxf(acc.x * r + b4.x, 0.f);
    v.y = fmaxf(acc.y * r + b4.y, 0.f);
    v.z = fmaxf(acc.z * r + b4.z, 0.f);
    v.w = fmaxf(acc.w * r + b4.w, 0.f);

    // mean over heads: sum lanes l, l^8, l^16, l^24
#pragma unroll
    for (int d = 8; d <= 16; d <<= 1) {
        v.x += __shfl_xor_sync(0xffffffffu, v.x, d);
        v.y += __shfl_xor_sync(0xffffffffu, v.y, d);
        v.z += __shfl_xor_sync(0xffffffffu, v.z, d);
        v.w += __shfl_xor_sync(0xffffffffu, v.w, d);
    }
    if (lane < 8) {
        v.x *= 0.25f; v.y *= 0.25f; v.z *= 0.25f; v.w *= 0.25f;
        ((float4*)out)[w * 8 + lane] = v;
    }
}

// ---------------- launch ----------------------------------------------------
extern "C" void kernel_launch(void* const* d_in, const int* in_sizes, int n_in,
                              void* d_out, int out_size) {
    const float* h    = (const float*)d_in[0];
    const float* W    = (const float*)d_in[1];
    const float* al   = (const float*)d_in[2];
    const float* ar   = (const float*)d_in[3];
    const float* bias = (const float*)d_in[4];
    const int*   src  = (const int*)d_in[5];
    const int*   dst  = (const int*)d_in[6];
    float*       out  = (float*)d_out;

    k_init<<<(NN + 255) / 256, 256>>>();
    k_gemm<<<(NN + 63) / 64, 256>>>(h, W, al, ar);
    k_hist<<<(NE + 255) / 256, 256>>>(dst);
    k_scan<<<1, 1024>>>();
    k_scatter<<<(NE + 255) / 256, 256>>>(src, dst);
    k_agg<<<(NN * 32 + 255) / 256, 256>>>(bias, out);
}

// round 4
// speedup vs baseline: 2.6913x; 1.5416x over previous
#include <cuda_runtime.h>
#include <cuda_fp16.h>

#define NN 50000
#define NE 1600000
#define HF 128
#define NH 4
#define NF 32
#define SCAN_B 256
#define SCAN_NB ((NN + SCAN_B - 1) / SCAN_B)   // 196

// ---------------- device scratch ------------------------------------------
__device__ __half2 g_feath[(size_t)NN * 64];  // projected features fp16 [N,128]
__device__ float   g_el[NN * NH];             // left attention halves [N,4]
__device__ float   g_er[NN * NH];             // right attention halves [N,4]
__device__ int     g_deg[NN];                 // in-degree histogram
__device__ int     g_off[NN + 1];             // CSR row offsets (by dst)
__device__ int     g_cursor[NN];              // scatter cursors
__device__ int     g_csr_src[NE];             // src ids grouped by dst
__device__ int     g_bsum[SCAN_NB];           // per-block scan totals

__device__ __forceinline__ float lrelu(float x) {
    return x > 0.f ? x : 0.2f * x;
}

// ---------------- init: zero degree histogram ------------------------------
__global__ void k_init() {
    int i = blockIdx.x * blockDim.x + threadIdx.x;
    if (i < NN) g_deg[i] = 0;
}

// ---------------- GEMM: feat = h @ W, fused el/er epilogue ------------------
__global__ void __launch_bounds__(256) k_gemm(const float* __restrict__ h,
                                              const float* __restrict__ W,
                                              const float* __restrict__ attn_l,
                                              const float* __restrict__ attn_r) {
    __shared__ float  As[16][68];
    __shared__ float4 Ws[16 * 32];

    int tid = threadIdx.x;
    int tx = tid & 31;
    int ty = tid >> 5;
    int base = blockIdx.x * 64;
    int arow = tid >> 2;
    int aq   = tid & 3;

    float acc[8][4];
#pragma unroll
    for (int i = 0; i < 8; i++)
#pragma unroll
        for (int j = 0; j < 4; j++) acc[i][j] = 0.f;

    for (int k0 = 0; k0 < 128; k0 += 16) {
        float4 av = make_float4(0.f, 0.f, 0.f, 0.f);
        int gr = base + arow;
        if (gr < NN) av = *(const float4*)&h[gr * 128 + k0 + aq * 4];
        As[aq * 4 + 0][arow] = av.x;
        As[aq * 4 + 1][arow] = av.y;
        As[aq * 4 + 2][arow] = av.z;
        As[aq * 4 + 3][arow] = av.w;
        Ws[ty * 32 + tx]       = ((const float4*)W)[(k0 + ty) * 32 + tx];
        Ws[(ty + 8) * 32 + tx] = ((const float4*)W)[(k0 + ty + 8) * 32 + tx];
        __syncthreads();

#pragma unroll
        for (int kk = 0; kk < 16; kk++) {
            float4 a0 = *(const float4*)&As[kk][ty * 8];
            float4 a1 = *(const float4*)&As[kk][ty * 8 + 4];
            float4 b  = Ws[kk * 32 + tx];
            float av8[8] = {a0.x, a0.y, a0.z, a0.w, a1.x, a1.y, a1.z, a1.w};
#pragma unroll
            for (int i = 0; i < 8; i++) {
                acc[i][0] += av8[i] * b.x;
                acc[i][1] += av8[i] * b.y;
                acc[i][2] += av8[i] * b.z;
                acc[i][3] += av8[i] * b.w;
            }
        }
        __syncthreads();
    }

    float4 al = ((const float4*)attn_l)[tx];
    float4 ar = ((const float4*)attn_r)[tx];
    int hh = tx >> 3;

#pragma unroll
    for (int i = 0; i < 8; i++) {
        int gr = base + ty * 8 + i;
        bool valid = (gr < NN);

        __half2 h0 = __floats2half2_rn(acc[i][0], acc[i][1]);
        __half2 h1 = __floats2half2_rn(acc[i][2], acc[i][3]);
        if (valid) {
            uint2 u;
            u.x = *(unsigned*)&h0;
            u.y = *(unsigned*)&h1;
            ((uint2*)g_feath)[gr * 32 + tx] = u;
        }

        float pl = acc[i][0] * al.x + acc[i][1] * al.y + acc[i][2] * al.z + acc[i][3] * al.w;
        float pr = acc[i][0] * ar.x + acc[i][1] * ar.y + acc[i][2] * ar.z + acc[i][3] * ar.w;
#pragma unroll
        for (int d = 4; d >= 1; d >>= 1) {
            pl += __shfl_down_sync(0xffffffffu, pl, d, 8);
            pr += __shfl_down_sync(0xffffffffu, pr, d, 8);
        }
        if (valid && (tx & 7) == 0) {
            g_el[gr * 4 + hh] = pl;
            g_er[gr * 4 + hh] = pr;
        }
    }
}

// ---------------- CSR build: histogram ------------------------------------
__global__ void k_hist(const int* __restrict__ dst) {
    int e = blockIdx.x * blockDim.x + threadIdx.x;
    if (e < NE) atomicAdd(&g_deg[dst[e]], 1);
}

// ---------------- CSR build: multi-block exclusive scan ---------------------
// phase 1: per-block exclusive scan of g_deg, local prefixes -> g_off,
//          block total -> g_bsum
__global__ void __launch_bounds__(SCAN_B) k_scan1() {
    __shared__ int ss[SCAN_B];
    int t = threadIdx.x;
    int i = blockIdx.x * SCAN_B + t;
    int v = (i < NN) ? g_deg[i] : 0;
    ss[t] = v;
    __syncthreads();
#pragma unroll
    for (int off = 1; off < SCAN_B; off <<= 1) {
        int u = (t >= off) ? ss[t - off] : 0;
        __syncthreads();
        ss[t] += u;
        __syncthreads();
    }
    if (i < NN) g_off[i] = ss[t] - v;          // exclusive prefix within block
    if (t == SCAN_B - 1) g_bsum[blockIdx.x] = ss[t];
}

// phase 2: scan the block totals (SCAN_NB=196 values, one small block)
__global__ void __launch_bounds__(SCAN_B) k_scan2() {
    __shared__ int ss[SCAN_B];
    int t = threadIdx.x;
    int v = (t < SCAN_NB) ? g_bsum[t] : 0;
    ss[t] = v;
    __syncthreads();
#pragma unroll
    for (int off = 1; off < SCAN_B; off <<= 1) {
        int u = (t >= off) ? ss[t - off] : 0;
        __syncthreads();
        ss[t] += u;
        __syncthreads();
    }
    if (t < SCAN_NB) g_bsum[t] = ss[t] - v;    // exclusive prefix of blocks
}

// phase 3: add block base, mirror to cursor, set sentinel
__global__ void __launch_bounds__(SCAN_B) k_scan3() {
    int i = blockIdx.x * SCAN_B + threadIdx.x;
    if (i < NN) {
        int o = g_off[i] + g_bsum[blockIdx.x];
        g_off[i]    = o;
        g_cursor[i] = o;
    }
    if (i == 0) g_off[NN] = NE;
}

// ---------------- CSR build: scatter src ids grouped by dst -----------------
__global__ void k_scatter(const int* __restrict__ src, const int* __restrict__ dst) {
    int e = blockIdx.x * blockDim.x + threadIdx.x;
    if (e >= NE) return;
    int d = dst[e];
    int pos = atomicAdd(&g_cursor[d], 1);
    g_csr_src[pos] = src[e];
}

// ---------------- fused aggregate: softmax + fp16 gather + epilogue ---------
__global__ void __launch_bounds__(256) k_agg(const float* __restrict__ bias,
                                             float* __restrict__ out) {
    __shared__ int   s_s[8][32];
    __shared__ float s_ex[8][4][32];

    int w    = (blockIdx.x * blockDim.x + threadIdx.x) >> 5;
    int lane = threadIdx.x & 31;
    int wl   = threadIdx.x >> 5;
    if (w >= NN) return;

    int start = g_off[w];
    int end   = g_off[w + 1];
    float4 erd = ((const float4*)g_er)[w];
    int hh = lane >> 3;

    float4 acc  = make_float4(0.f, 0.f, 0.f, 0.f);
    float4 dsum = make_float4(0.f, 0.f, 0.f, 0.f);

    for (int base = start; base < end; base += 32) {
        int e = base + lane;
        int s = 0;
        float4 ex4 = make_float4(0.f, 0.f, 0.f, 0.f);
        if (e < end) {
            s = __ldg(&g_csr_src[e]);
            float4 a = ((const float4*)g_el)[s];
            ex4.x = __expf(lrelu(a.x + erd.x));
            ex4.y = __expf(lrelu(a.y + erd.y));
            ex4.z = __expf(lrelu(a.z + erd.z));
            ex4.w = __expf(lrelu(a.w + erd.w));
            dsum.x += ex4.x; dsum.y += ex4.y; dsum.z += ex4.z; dsum.w += ex4.w;
        }
        s_s[wl][lane]     = s;
        s_ex[wl][0][lane] = ex4.x;
        s_ex[wl][1][lane] = ex4.y;
        s_ex[wl][2][lane] = ex4.z;
        s_ex[wl][3][lane] = ex4.w;
        __syncwarp();

        int cnt = end - base;
        if (cnt > 32) cnt = 32;
#pragma unroll 4
        for (int j = 0; j < cnt; j++) {
            int   sj = s_s[wl][j];
            float aj = s_ex[wl][hh][j];
            uint2 u  = __ldg(&((const uint2*)g_feath)[sj * 32 + lane]);
            float2 f0 = __half22float2(*(__half2*)&u.x);
            float2 f1 = __half22float2(*(__half2*)&u.y);
            acc.x += f0.x * aj;
            acc.y += f0.y * aj;
            acc.z += f1.x * aj;
            acc.w += f1.y * aj;
        }
        __syncwarp();
    }

#pragma unroll
    for (int d = 16; d >= 1; d >>= 1) {
        dsum.x += __shfl_xor_sync(0xffffffffu, dsum.x, d);
        dsum.y += __shfl_xor_sync(0xffffffffu, dsum.y, d);
        dsum.z += __shfl_xor_sync(0xffffffffu, dsum.z, d);
        dsum.w += __shfl_xor_sync(0xffffffffu, dsum.w, d);
    }
    float dh = (hh == 0) ? dsum.x : (hh == 1) ? dsum.y : (hh == 2) ? dsum.z : dsum.w;
    float r  = 1.f / fmaxf(dh, 1e-9f);

    float4 b4 = ((const float4*)bias)[lane];
    float4 v;
    v.x = fmaxf(acc.x * r + b4.x, 0.f);
    v.y = fmaxf(acc.y * r + b4.y, 0.f);
    v.z = fmaxf(acc.z * r + b4.z, 0.f);
    v.w = fmaxf(acc.w * r + b4.w, 0.f);

#pragma unroll
    for (int d = 8; d <= 16; d <<= 1) {
        v.x += __shfl_xor_sync(0xffffffffu, v.x, d);
        v.y += __shfl_xor_sync(0xffffffffu, v.y, d);
        v.z += __shfl_xor_sync(0xffffffffu, v.z, d);
        v.w += __shfl_xor_sync(0xffffffffu, v.w, d);
    }
    if (lane < 8) {
        v.x *= 0.25f; v.y *= 0.25f; v.z *= 0.25f; v.w *= 0.25f;
        ((float4*)out)[w * 8 + lane] = v;
    }
}

// ---------------- launch ----------------------------------------------------
extern "C" void kernel_launch(void* const* d_in, const int* in_sizes, int n_in,
                              void* d_out, int out_size) {
    const float* h    = (const float*)d_in[0];
    const float* W    = (const float*)d_in[1];
    const float* al   = (const float*)d_in[2];
    const float* ar   = (const float*)d_in[3];
    const float* bias = (const float*)d_in[4];
    const int*   src  = (const int*)d_in[5];
    const int*   dst  = (const int*)d_in[6];
    float*       out  = (float*)d_out;

    k_init<<<(NN + 255) / 256, 256>>>();
    k_gemm<<<(NN + 63) / 64, 256>>>(h, W, al, ar);
    k_hist<<<(NE + 255) / 256, 256>>>(dst);
    k_scan1<<<SCAN_NB, SCAN_B>>>();
    k_scan2<<<1, SCAN_B>>>();
    k_scan3<<<SCAN_NB, SCAN_B>>>();
    k_scatter<<<(NE + 255) / 256, 256>>>(src, dst);
    k_agg<<<(NN * 32 + 255) / 256, 256>>>(bias, out);
}

// round 5
// speedup vs baseline: 2.8257x; 1.0499x over previous
#include <cuda_runtime.h>
#include <cuda_fp16.h>

#define NN 50000
#define NE 1600000
#define HF 128
#define NH 4
#define NF 32
#define SCAN_B 256
#define SCAN_NB ((NN + SCAN_B - 1) / SCAN_B)   // 196

// ---------------- device scratch ------------------------------------------
__device__ __half2 g_feath[(size_t)NN * 64];  // projected features fp16 [N,128]
__device__ float   g_el[NN * NH];             // left attention halves [N,4]
__device__ float   g_er[NN * NH];             // right attention halves [N,4]
__device__ int     g_deg[NN];                 // in-degree histogram
__device__ int     g_off[NN + 1];             // CSR row offsets (by dst)
__device__ int     g_cursor[NN];              // scatter cursors
__device__ int     g_csr_src[NE];             // src ids grouped by dst
__device__ int     g_bsum[SCAN_NB];           // per-block scan totals

__device__ __forceinline__ float lrelu(float x) {
    return x > 0.f ? x : 0.2f * x;
}

// ---------------- init: zero degree histogram ------------------------------
__global__ void k_init() {
    int i = blockIdx.x * blockDim.x + threadIdx.x;
    if (i < NN) g_deg[i] = 0;
}

// ---------------- GEMM: feat = h @ W, fused el/er epilogue ------------------
__global__ void __launch_bounds__(256) k_gemm(const float* __restrict__ h,
                                              const float* __restrict__ W,
                                              const float* __restrict__ attn_l,
                                              const float* __restrict__ attn_r) {
    __shared__ float  As[16][68];
    __shared__ float4 Ws[16 * 32];

    int tid = threadIdx.x;
    int tx = tid & 31;
    int ty = tid >> 5;
    int base = blockIdx.x * 64;
    int arow = tid >> 2;
    int aq   = tid & 3;

    float acc[8][4];
#pragma unroll
    for (int i = 0; i < 8; i++)
#pragma unroll
        for (int j = 0; j < 4; j++) acc[i][j] = 0.f;

    for (int k0 = 0; k0 < 128; k0 += 16) {
        float4 av = make_float4(0.f, 0.f, 0.f, 0.f);
        int gr = base + arow;
        if (gr < NN) av = *(const float4*)&h[gr * 128 + k0 + aq * 4];
        As[aq * 4 + 0][arow] = av.x;
        As[aq * 4 + 1][arow] = av.y;
        As[aq * 4 + 2][arow] = av.z;
        As[aq * 4 + 3][arow] = av.w;
        Ws[ty * 32 + tx]       = ((const float4*)W)[(k0 + ty) * 32 + tx];
        Ws[(ty + 8) * 32 + tx] = ((const float4*)W)[(k0 + ty + 8) * 32 + tx];
        __syncthreads();

#pragma unroll
        for (int kk = 0; kk < 16; kk++) {
            float4 a0 = *(const float4*)&As[kk][ty * 8];
            float4 a1 = *(const float4*)&As[kk][ty * 8 + 4];
            float4 b  = Ws[kk * 32 + tx];
            float av8[8] = {a0.x, a0.y, a0.z, a0.w, a1.x, a1.y, a1.z, a1.w};
#pragma unroll
            for (int i = 0; i < 8; i++) {
                acc[i][0] += av8[i] * b.x;
                acc[i][1] += av8[i] * b.y;
                acc[i][2] += av8[i] * b.z;
                acc[i][3] += av8[i] * b.w;
            }
        }
        __syncthreads();
    }

    float4 al = ((const float4*)attn_l)[tx];
    float4 ar = ((const float4*)attn_r)[tx];
    int hh = tx >> 3;

#pragma unroll
    for (int i = 0; i < 8; i++) {
        int gr = base + ty * 8 + i;
        bool valid = (gr < NN);

        __half2 h0 = __floats2half2_rn(acc[i][0], acc[i][1]);
        __half2 h1 = __floats2half2_rn(acc[i][2], acc[i][3]);
        if (valid) {
            uint2 u;
            u.x = *(unsigned*)&h0;
            u.y = *(unsigned*)&h1;
            ((uint2*)g_feath)[gr * 32 + tx] = u;
        }

        float pl = acc[i][0] * al.x + acc[i][1] * al.y + acc[i][2] * al.z + acc[i][3] * al.w;
        float pr = acc[i][0] * ar.x + acc[i][1] * ar.y + acc[i][2] * ar.z + acc[i][3] * ar.w;
#pragma unroll
        for (int d = 4; d >= 1; d >>= 1) {
            pl += __shfl_down_sync(0xffffffffu, pl, d, 8);
            pr += __shfl_down_sync(0xffffffffu, pr, d, 8);
        }
        if (valid && (tx & 7) == 0) {
            g_el[gr * 4 + hh] = pl;
            g_er[gr * 4 + hh] = pr;
        }
    }
}

// ---------------- CSR build: histogram (4 edges/thread) ---------------------
__global__ void k_hist(const int* __restrict__ dst) {
    int q = blockIdx.x * blockDim.x + threadIdx.x;   // NE/4 quads
    if (q >= NE / 4) return;
    int4 d4 = ((const int4*)dst)[q];
    atomicAdd(&g_deg[d4.x], 1);
    atomicAdd(&g_deg[d4.y], 1);
    atomicAdd(&g_deg[d4.z], 1);
    atomicAdd(&g_deg[d4.w], 1);
}

// ---------------- CSR build: multi-block exclusive scan ---------------------
__global__ void __launch_bounds__(SCAN_B) k_scan1() {
    __shared__ int ss[SCAN_B];
    int t = threadIdx.x;
    int i = blockIdx.x * SCAN_B + t;
    int v = (i < NN) ? g_deg[i] : 0;
    ss[t] = v;
    __syncthreads();
#pragma unroll
    for (int off = 1; off < SCAN_B; off <<= 1) {
        int u = (t >= off) ? ss[t - off] : 0;
        __syncthreads();
        ss[t] += u;
        __syncthreads();
    }
    if (i < NN) g_off[i] = ss[t] - v;
    if (t == SCAN_B - 1) g_bsum[blockIdx.x] = ss[t];
}

__global__ void __launch_bounds__(SCAN_B) k_scan2() {
    __shared__ int ss[SCAN_B];
    int t = threadIdx.x;
    int v = (t < SCAN_NB) ? g_bsum[t] : 0;
    ss[t] = v;
    __syncthreads();
#pragma unroll
    for (int off = 1; off < SCAN_B; off <<= 1) {
        int u = (t >= off) ? ss[t - off] : 0;
        __syncthreads();
        ss[t] += u;
        __syncthreads();
    }
    if (t < SCAN_NB) g_bsum[t] = ss[t] - v;
}

__global__ void __launch_bounds__(SCAN_B) k_scan3() {
    int i = blockIdx.x * SCAN_B + threadIdx.x;
    if (i < NN) {
        int o = g_off[i] + g_bsum[blockIdx.x];
        g_off[i]    = o;
        g_cursor[i] = o;
    }
    if (i == 0) g_off[NN] = NE;
}

// ---------------- CSR build: scatter (4 edges/thread) -----------------------
__global__ void k_scatter(const int* __restrict__ src, const int* __restrict__ dst) {
    int q = blockIdx.x * blockDim.x + threadIdx.x;
    if (q >= NE / 4) return;
    int4 s4 = ((const int4*)src)[q];
    int4 d4 = ((const int4*)dst)[q];
    g_csr_src[atomicAdd(&g_cursor[d4.x], 1)] = s4.x;
    g_csr_src[atomicAdd(&g_cursor[d4.y], 1)] = s4.y;
    g_csr_src[atomicAdd(&g_cursor[d4.z], 1)] = s4.z;
    g_csr_src[atomicAdd(&g_cursor[d4.w], 1)] = s4.w;
}

// ---------------- fused aggregate: softmax + fp16 gather + epilogue ---------
__global__ void __launch_bounds__(256) k_agg(const float* __restrict__ bias,
                                             float* __restrict__ out) {
    __shared__ int   s_s[8][32];
    __shared__ float s_ex[8][4][32];

    int w    = (blockIdx.x * blockDim.x + threadIdx.x) >> 5;
    int lane = threadIdx.x & 31;
    int wl   = threadIdx.x >> 5;
    if (w >= NN) return;

    int start = g_off[w];
    int end   = g_off[w + 1];
    float4 erd = ((const float4*)g_er)[w];
    int hh = lane >> 3;

    float4 acc  = make_float4(0.f, 0.f, 0.f, 0.f);
    float4 dsum = make_float4(0.f, 0.f, 0.f, 0.f);

    for (int base = start; base < end; base += 32) {
        int e = base + lane;
        int s = 0;
        float4 ex4 = make_float4(0.f, 0.f, 0.f, 0.f);
        if (e < end) {
            s = __ldg(&g_csr_src[e]);
            float4 a = ((const float4*)g_el)[s];
            ex4.x = __expf(lrelu(a.x + erd.x));
            ex4.y = __expf(lrelu(a.y + erd.y));
            ex4.z = __expf(lrelu(a.z + erd.z));
            ex4.w = __expf(lrelu(a.w + erd.w));
            dsum.x += ex4.x; dsum.y += ex4.y; dsum.z += ex4.z; dsum.w += ex4.w;
        }
        s_s[wl][lane]     = s;
        s_ex[wl][0][lane] = ex4.x;
        s_ex[wl][1][lane] = ex4.y;
        s_ex[wl][2][lane] = ex4.z;
        s_ex[wl][3][lane] = ex4.w;
        __syncwarp();

        int cnt = end - base;
        if (cnt > 32) cnt = 32;
#pragma unroll 8
        for (int j = 0; j < cnt; j++) {
            int   sj = s_s[wl][j];
            float aj = s_ex[wl][hh][j];
            uint2 u  = __ldg(&((const uint2*)g_feath)[sj * 32 + lane]);
            float2 f0 = __half22float2(*(__half2*)&u.x);
            float2 f1 = __half22float2(*(__half2*)&u.y);
            acc.x += f0.x * aj;
            acc.y += f0.y * aj;
            acc.z += f1.x * aj;
            acc.w += f1.y * aj;
        }
        __syncwarp();
    }

#pragma unroll
    for (int d = 16; d >= 1; d >>= 1) {
        dsum.x += __shfl_xor_sync(0xffffffffu, dsum.x, d);
        dsum.y += __shfl_xor_sync(0xffffffffu, dsum.y, d);
        dsum.z += __shfl_xor_sync(0xffffffffu, dsum.z, d);
        dsum.w += __shfl_xor_sync(0xffffffffu, dsum.w, d);
    }
    float dh = (hh == 0) ? dsum.x : (hh == 1) ? dsum.y : (hh == 2) ? dsum.z : dsum.w;
    float r  = 1.f / fmaxf(dh, 1e-9f);

    float4 b4 = ((const float4*)bias)[lane];
    float4 v;
    v.x = fmaxf(acc.x * r + b4.x, 0.f);
    v.y = fmaxf(acc.y * r + b4.y, 0.f);
    v.z = fmaxf(acc.z * r + b4.z, 0.f);
    v.w = fmaxf(acc.w * r + b4.w, 0.f);

#pragma unroll
    for (int d = 8; d <= 16; d <<= 1) {
        v.x += __shfl_xor_sync(0xffffffffu, v.x, d);
        v.y += __shfl_xor_sync(0xffffffffu, v.y, d);
        v.z += __shfl_xor_sync(0xffffffffu, v.z, d);
        v.w += __shfl_xor_sync(0xffffffffu, v.w, d);
    }
    if (lane < 8) {
        v.x *= 0.25f; v.y *= 0.25f; v.z *= 0.25f; v.w *= 0.25f;
        ((float4*)out)[w * 8 + lane] = v;
    }
}

// ---------------- launch: fork-join overlap of GEMM and CSR build -----------
extern "C" void kernel_launch(void* const* d_in, const int* in_sizes, int n_in,
                              void* d_out, int out_size) {
    const float* h    = (const float*)d_in[0];
    const float* W    = (const float*)d_in[1];
    const float* al   = (const float*)d_in[2];
    const float* ar   = (const float*)d_in[3];
    const float* bias = (const float*)d_in[4];
    const int*   src  = (const int*)d_in[5];
    const int*   dst  = (const int*)d_in[6];
    float*       out  = (float*)d_out;

    // one-time infra (created on first, non-captured, correctness call;
    // reused identically on every call — work is deterministic)
    static cudaStream_t s2 = 0;
    static cudaEvent_t evFork = 0, evJoin = 0;
    if (!s2) {
        cudaStreamCreateWithFlags(&s2, cudaStreamNonBlocking);
        cudaEventCreateWithFlags(&evFork, cudaEventDisableTiming);
        cudaEventCreateWithFlags(&evJoin, cudaEventDisableTiming);
    }

    // fork: gemm branch on s2, CSR branch on capture (default) stream
    cudaEventRecord(evFork, 0);
    cudaStreamWaitEvent(s2, evFork, 0);
    k_gemm<<<(NN + 63) / 64, 256, 0, s2>>>(h, W, al, ar);
    cudaEventRecord(evJoin, s2);

    k_init<<<(NN + 255) / 256, 256>>>();
    k_hist<<<(NE / 4 + 255) / 256, 256>>>(dst);
    k_scan1<<<SCAN_NB, SCAN_B>>>();
    k_scan2<<<1, SCAN_B>>>();
    k_scan3<<<SCAN_NB, SCAN_B>>>();
    k_scatter<<<(NE / 4 + 255) / 256, 256>>>(src, dst);

    // join: agg needs both branches
    cudaStreamWaitEvent(0, evJoin, 0);
    k_agg<<<(NN * 32 + 255) / 256, 256>>>(bias, out);
}

// round 7
// speedup vs baseline: 3.2289x; 1.1427x over previous
#include <cuda_runtime.h>
#include <cuda_fp16.h>
#include <cstdint>

#define NN 50000
#define NE 1600000
#define HF 128
#define NH 4
#define NF 32
#define SCAN_B 256
#define SCAN_NB ((NN + SCAN_B - 1) / SCAN_B)   // 196
#define GEMM_TILE 128
#define GEMM_NB ((NN + GEMM_TILE - 1) / GEMM_TILE)  // 391

// smem: A/B fp16 tiles with 136-half stride (272B rows, 16B aligned, ldmatrix-safe)
#define TSTRIDE 136
#define TILE_HB (128 * TSTRIDE * 2)     // 34816 bytes per tile
#define SM_TOT  (2 * TILE_HB)           // 69632 bytes

// ---------------- device scratch ------------------------------------------
__device__ __half2 g_feath[(size_t)NN * 64];  // projected features fp16 [N,128]
__device__ float   g_el[NN * NH];             // left attention halves [N,4]
__device__ float   g_er[NN * NH];             // right attention halves [N,4]
__device__ int     g_deg[NN];                 // in-degree histogram
__device__ int     g_off[NN + 1];             // CSR row offsets (by dst)
__device__ int     g_cursor[NN];              // scatter cursors
__device__ int     g_csr_src[NE];             // src ids grouped by dst
__device__ int     g_bsum[SCAN_NB];           // per-block scan totals

__device__ __forceinline__ float lrelu(float x) {
    return x > 0.f ? x : 0.2f * x;
}

__device__ __forceinline__ uint32_t smem_u32(const void* p) {
    uint32_t a;
    asm("{ .reg .u64 t; cvta.to.shared.u64 t, %1; cvt.u32.u64 %0, t; }" : "=r"(a) : "l"(p));
    return a;
}

__device__ __forceinline__ void ldsm_x4(uint32_t addr, uint32_t* r) {
    asm volatile("ldmatrix.sync.aligned.m8n8.x4.shared.b16 {%0,%1,%2,%3}, [%4];"
                 : "=r"(r[0]), "=r"(r[1]), "=r"(r[2]), "=r"(r[3]) : "r"(addr));
}
__device__ __forceinline__ void ldsm_x2(uint32_t addr, uint32_t* r) {
    asm volatile("ldmatrix.sync.aligned.m8n8.x2.shared.b16 {%0,%1}, [%2];"
                 : "=r"(r[0]), "=r"(r[1]) : "r"(addr));
}
__device__ __forceinline__ void mma16816(float* c, const uint32_t* a, const uint32_t* b) {
    asm volatile(
        "mma.sync.aligned.m16n8k16.row.col.f32.f16.f16.f32 "
        "{%0,%1,%2,%3}, {%4,%5,%6,%7}, {%8,%9}, {%0,%1,%2,%3};"
        : "+f"(c[0]), "+f"(c[1]), "+f"(c[2]), "+f"(c[3])
        : "r"(a[0]), "r"(a[1]), "r"(a[2]), "r"(a[3]), "r"(b[0]), "r"(b[1]));
}

// ---------------- init ------------------------------------------------------
__global__ void k_init() {
    int i = blockIdx.x * blockDim.x + threadIdx.x;
    if (i < NN) g_deg[i] = 0;
}

// ---------------- HMMA GEMM: feat = h @ W, fused el/er ----------------------
// 128 rows/CTA, 256 threads (8 warps). Warp w: M-rows [(w>>1)*32, +32),
// N-cols [(w&1)*64, +64). fp16 inputs, fp32 accumulators.
__global__ void __launch_bounds__(256) k_gemm(const float* __restrict__ h,
                                              const float* __restrict__ W,
                                              const float* __restrict__ attn_l,
                                              const float* __restrict__ attn_r) {
    extern __shared__ char smem[];
    __half* As = (__half*)smem;                 // [128][TSTRIDE] row-major (m x k)
    __half* Bs = (__half*)(smem + TILE_HB);     // [128][TSTRIDE] = Wt (n x k) = col-major B
    uint32_t sA = smem_u32(As);
    uint32_t sB = smem_u32(Bs);

    int tid  = threadIdx.x;
    int wid  = tid >> 5;
    int lane = tid & 31;
    int base = blockIdx.x * GEMM_TILE;

    // A fill: h rows [base, base+128) fp32 -> fp16, row-major
    for (int p = tid; p < 128 * 64; p += 256) {
        int r  = p >> 6;
        int c2 = p & 63;             // half2 index within row
        float2 v = make_float2(0.f, 0.f);
        int gr = base + r;
        if (gr < NN) v = *(const float2*)&h[(size_t)gr * 128 + c2 * 2];
        *(__half2*)&As[r * TSTRIDE + c2 * 2] = __floats2half2_rn(v.x, v.y);
    }
    // B fill: Bs[n][k] = W[k][n] (coalesced W reads, scattered smem stores)
    for (int p = tid; p < 128 * 64; p += 256) {
        int k  = p >> 6;
        int n2 = p & 63;
        float2 v = *(const float2*)&W[(size_t)k * 128 + n2 * 2];
        Bs[(n2 * 2)     * TSTRIDE + k] = __float2half_rn(v.x);
        Bs[(n2 * 2 + 1) * TSTRIDE + k] = __float2half_rn(v.y);
    }
    __syncthreads();

    int mrow0 = (wid >> 1) * 32;
    int ncol0 = (wid & 1) * 64;

    float acc[2][8][4];
#pragma unroll
    for (int mi = 0; mi < 2; mi++)
#pragma unroll
        for (int ni = 0; ni < 8; ni++)
#pragma unroll
            for (int j = 0; j < 4; j++) acc[mi][ni][j] = 0.f;

#pragma unroll
    for (int ks = 0; ks < 8; ks++) {
        int k0 = ks * 16;
        uint32_t a[2][4];
#pragma unroll
        for (int mi = 0; mi < 2; mi++) {
            int row = mrow0 + mi * 16 + (lane & 15);
            int col = k0 + (lane >> 4) * 8;
            ldsm_x4(sA + (row * TSTRIDE + col) * 2, a[mi]);
        }
        uint32_t b[8][2];
#pragma unroll
        for (int ni = 0; ni < 8; ni++) {
            int n = ncol0 + ni * 8 + (lane & 7);
            int k = k0 + ((lane >> 3) & 1) * 8;
            ldsm_x2(sB + (n * TSTRIDE + k) * 2, b[ni]);
        }
#pragma unroll
        for (int mi = 0; mi < 2; mi++)
#pragma unroll
            for (int ni = 0; ni < 8; ni++)
                mma16816(acc[mi][ni], a[mi], b[ni]);
    }
    __syncthreads();   // done with A loads; reuse As as C staging

    // stage C (fp16) into As region, stride TSTRIDE
    __half* Cs = As;
#pragma unroll
    for (int mi = 0; mi < 2; mi++) {
        int r0 = mrow0 + mi * 16 + (lane >> 2);
#pragma unroll
        for (int ni = 0; ni < 8; ni++) {
            int cb = ncol0 + ni * 8 + (lane & 3) * 2;
            *(__half2*)&Cs[r0 * TSTRIDE + cb]       = __floats2half2_rn(acc[mi][ni][0], acc[mi][ni][1]);
            *(__half2*)&Cs[(r0 + 8) * TSTRIDE + cb] = __floats2half2_rn(acc[mi][ni][2], acc[mi][ni][3]);
        }
    }
    __syncthreads();

    // epilogue: warp w handles rows [w*16, w*16+16); lane covers cols lane*4..+3
    float4 al = ((const float4*)attn_l)[lane];
    float4 ar = ((const float4*)attn_r)[lane];
    int hh = lane >> 3;

    for (int i = 0; i < 16; i++) {
        int r  = wid * 16 + i;
        int gr = base + r;
        uint2 u = *(uint2*)&Cs[r * TSTRIDE + lane * 4];
        float2 f0 = __half22float2(*(__half2*)&u.x);
        float2 f1 = __half22float2(*(__half2*)&u.y);
        if (gr < NN) ((uint2*)g_feath)[(size_t)gr * 32 + lane] = u;

        float pl = f0.x * al.x + f0.y * al.y + f1.x * al.z + f1.y * al.w;
        float pr = f0.x * ar.x + f0.y * ar.y + f1.x * ar.z + f1.y * ar.w;
#pragma unroll
        for (int d = 4; d >= 1; d >>= 1) {
            pl += __shfl_down_sync(0xffffffffu, pl, d, 8);
            pr += __shfl_down_sync(0xffffffffu, pr, d, 8);
        }
        if (gr < NN && (lane & 7) == 0) {
            g_el[gr * 4 + hh] = pl;
            g_er[gr * 4 + hh] = pr;
        }
    }
}

// ---------------- CSR build: histogram (4 edges/thread) ---------------------
__global__ void k_hist(const int* __restrict__ dst) {
    int q = blockIdx.x * blockDim.x + threadIdx.x;
    if (q >= NE / 4) return;
    int4 d4 = ((const int4*)dst)[q];
    atomicAdd(&g_deg[d4.x], 1);
    atomicAdd(&g_deg[d4.y], 1);
    atomicAdd(&g_deg[d4.z], 1);
    atomicAdd(&g_deg[d4.w], 1);
}

// ---------------- CSR build: multi-block exclusive scan ---------------------
__global__ void __launch_bounds__(SCAN_B) k_scan1() {
    __shared__ int ss[SCAN_B];
    int t = threadIdx.x;
    int i = blockIdx.x * SCAN_B + t;
    int v = (i < NN) ? g_deg[i] : 0;
    ss[t] = v;
    __syncthreads();
#pragma unroll
    for (int off = 1; off < SCAN_B; off <<= 1) {
        int u = (t >= off) ? ss[t - off] : 0;
        __syncthreads();
        ss[t] += u;
        __syncthreads();
    }
    if (i < NN) g_off[i] = ss[t] - v;
    if (t == SCAN_B - 1) g_bsum[blockIdx.x] = ss[t];
}

__global__ void __launch_bounds__(SCAN_B) k_scan2() {
    __shared__ int ss[SCAN_B];
    int t = threadIdx.x;
    int v = (t < SCAN_NB) ? g_bsum[t] : 0;
    ss[t] = v;
    __syncthreads();
#pragma unroll
    for (int off = 1; off < SCAN_B; off <<= 1) {
        int u = (t >= off) ? ss[t - off] : 0;
        __syncthreads();
        ss[t] += u;
        __syncthreads();
    }
    if (t < SCAN_NB) g_bsum[t] = ss[t] - v;
}

__global__ void __launch_bounds__(SCAN_B) k_scan3() {
    int i = blockIdx.x * SCAN_B + threadIdx.x;
    if (i < NN) {
        int o = g_off[i] + g_bsum[blockIdx.x];
        g_off[i]    = o;
        g_cursor[i] = o;
    }
    if (i == 0) g_off[NN] = NE;
}

// ---------------- CSR build: scatter (4 edges/thread) -----------------------
__global__ void k_scatter(const int* __restrict__ src, const int* __restrict__ dst) {
    int q = blockIdx.x * blockDim.x + threadIdx.x;
    if (q >= NE / 4) return;
    int4 s4 = ((const int4*)src)[q];
    int4 d4 = ((const int4*)dst)[q];
    g_csr_src[atomicAdd(&g_cursor[d4.x], 1)] = s4.x;
    g_csr_src[atomicAdd(&g_cursor[d4.y], 1)] = s4.y;
    g_csr_src[atomicAdd(&g_cursor[d4.z], 1)] = s4.z;
    g_csr_src[atomicAdd(&g_cursor[d4.w], 1)] = s4.w;
}

// ---------------- fused aggregate: softmax + fp16 gather + epilogue ---------
__global__ void __launch_bounds__(256) k_agg(const float* __restrict__ bias,
                                             float* __restrict__ out) {
    __shared__ int   s_s[8][32];
    __shared__ float s_ex[8][4][32];

    int w    = (blockIdx.x * blockDim.x + threadIdx.x) >> 5;
    int lane = threadIdx.x & 31;
    int wl   = threadIdx.x >> 5;
    if (w >= NN) return;

    int start = g_off[w];
    int end   = g_off[w + 1];
    float4 erd = ((const float4*)g_er)[w];
    int hh = lane >> 3;

    float4 acc  = make_float4(0.f, 0.f, 0.f, 0.f);
    float4 dsum = make_float4(0.f, 0.f, 0.f, 0.f);

    for (int base = start; base < end; base += 32) {
        int e = base + lane;
        int s = 0;
        float4 ex4 = make_float4(0.f, 0.f, 0.f, 0.f);
        if (e < end) {
            s = __ldg(&g_csr_src[e]);
            float4 a = ((const float4*)g_el)[s];
            ex4.x = __expf(lrelu(a.x + erd.x));
            ex4.y = __expf(lrelu(a.y + erd.y));
            ex4.z = __expf(lrelu(a.z + erd.z));
            ex4.w = __expf(lrelu(a.w + erd.w));
            dsum.x += ex4.x; dsum.y += ex4.y; dsum.z += ex4.z; dsum.w += ex4.w;
        }
        s_s[wl][lane]     = s;
        s_ex[wl][0][lane] = ex4.x;
        s_ex[wl][1][lane] = ex4.y;
        s_ex[wl][2][lane] = ex4.z;
        s_ex[wl][3][lane] = ex4.w;
        __syncwarp();

        int cnt = end - base;
        if (cnt > 32) cnt = 32;
#pragma unroll 8
        for (int j = 0; j < cnt; j++) {
            int   sj = s_s[wl][j];
            float aj = s_ex[wl][hh][j];
            uint2 u  = __ldg(&((const uint2*)g_feath)[(size_t)sj * 32 + lane]);
            float2 f0 = __half22float2(*(__half2*)&u.x);
            float2 f1 = __half22float2(*(__half2*)&u.y);
            acc.x += f0.x * aj;
            acc.y += f0.y * aj;
            acc.z += f1.x * aj;
            acc.w += f1.y * aj;
        }
        __syncwarp();
    }

#pragma unroll
    for (int d = 16; d >= 1; d >>= 1) {
        dsum.x += __shfl_xor_sync(0xffffffffu, dsum.x, d);
        dsum.y += __shfl_xor_sync(0xffffffffu, dsum.y, d);
        dsum.z += __shfl_xor_sync(0xffffffffu, dsum.z, d);
        dsum.w += __shfl_xor_sync(0xffffffffu, dsum.w, d);
    }
    float dh = (hh == 0) ? dsum.x : (hh == 1) ? dsum.y : (hh == 2) ? dsum.z : dsum.w;
    float r  = 1.f / fmaxf(dh, 1e-9f);

    float4 b4 = ((const float4*)bias)[lane];
    float4 v;
    v.x = fmaxf(acc.x * r + b4.x, 0.f);
    v.y = fmaxf(acc.y * r + b4.y, 0.f);
    v.z = fmaxf(acc.z * r + b4.z, 0.f);
    v.w = fmaxf(acc.w * r + b4.w, 0.f);

#pragma unroll
    for (int d = 8; d <= 16; d <<= 1) {
        v.x += __shfl_xor_sync(0xffffffffu, v.x, d);
        v.y += __shfl_xor_sync(0xffffffffu, v.y, d);
        v.z += __shfl_xor_sync(0xffffffffu, v.z, d);
        v.w += __shfl_xor_sync(0xffffffffu, v.w, d);
    }
    if (lane < 8) {
        v.x *= 0.25f; v.y *= 0.25f; v.z *= 0.25f; v.w *= 0.25f;
        ((float4*)out)[w * 8 + lane] = v;
    }
}

// ---------------- launch ----------------------------------------------------
extern "C" void kernel_launch(void* const* d_in, const int* in_sizes, int n_in,
                              void* d_out, int out_size) {
    const float* h    = (const float*)d_in[0];
    const float* W    = (const float*)d_in[1];
    const float* al   = (const float*)d_in[2];
    const float* ar   = (const float*)d_in[3];
    const float* bias = (const float*)d_in[4];
    const int*   src  = (const int*)d_in[5];
    const int*   dst  = (const int*)d_in[6];
    float*       out  = (float*)d_out;

    static cudaStream_t s2 = 0;
    static cudaEvent_t evFork = 0, evJoin = 0;
    if (!s2) {
        cudaStreamCreateWithFlags(&s2, cudaStreamNonBlocking);
        cudaEventCreateWithFlags(&evFork, cudaEventDisableTiming);
        cudaEventCreateWithFlags(&evJoin, cudaEventDisableTiming);
        cudaFuncSetAttribute(k_gemm, cudaFuncAttributeMaxDynamicSharedMemorySize, SM_TOT);
    }

    // fork: HMMA gemm on s2, CSR branch on capture stream
    cudaEventRecord(evFork, 0);
    cudaStreamWaitEvent(s2, evFork, 0);
    k_gemm<<<GEMM_NB, 256, SM_TOT, s2>>>(h, W, al, ar);
    cudaEventRecord(evJoin, s2);

    k_init<<<(NN + 255) / 256, 256>>>();
    k_hist<<<(NE / 4 + 255) / 256, 256>>>(dst);
    k_scan1<<<SCAN_NB, SCAN_B>>>();
    k_scan2<<<1, SCAN_B>>>();
    k_scan3<<<SCAN_NB, SCAN_B>>>();
    k_scatter<<<(NE / 4 + 255) / 256, 256>>>(src, dst);

    cudaStreamWaitEvent(0, evJoin, 0);
    k_agg<<<(NN * 32 + 255) / 256, 256>>>(bias, out);
}